// round 15
// baseline (speedup 1.0000x reference)
#include <cuda_runtime.h>
#include <cuda_bf16.h>
#include <cstdint>
#include <math.h>

#define BB 32
#define TT 128
#define SSRC 128
#define HH 512
#define EE 256
#define VV 32000
#define K2H 1024
#define G4 2048
#define NBLK 128
#define NTILE 250
#define FSTR 32

typedef unsigned long long ull;

// ---------------- device scratch ----------------
static __device__ float g_keys[BB*SSRC*HH];
static __device__ float g_encdec[BB*SSRC*HH];        // [b][s][j]
static __device__ float g_gatesy[TT*BB*G4];
static __device__ float g_embseq[TT*BB*EE];
static __device__ float g_x[BB*K2H];                 // [o(512), h(512)]
static __device__ float g_pctx[4*BB*HH];             // [q][b][j]
static __device__ float2 g_bstats[4*BB];             // (m, Z)
static __device__ float g_oseq[BB*TT*HH];
static __device__ uint4 g_oswz[256*32*32];
static __device__ uint2 g_wswz[4000*32*32];
static __device__ float g_partial[(size_t)BB*TT*NTILE];
static __device__ unsigned g_flags[NBLK*FSTR];

static __device__ __forceinline__ uint32_t pk_bf2(float lo, float hi) {
    __nv_bfloat16 l = __float2bfloat16(lo), h = __float2bfloat16(hi);
    return (uint32_t)__bfloat16_as_ushort(l) | ((uint32_t)__bfloat16_as_ushort(h) << 16);
}
static __device__ __forceinline__ void ffma2(ull& acc, ull a, ull b) {
    asm volatile("fma.rn.f32x2 %0, %1, %2, %0;" : "+l"(acc) : "l"(a), "l"(b));
}
static __device__ __forceinline__ float2 u2f(ull v) {
    float2 f; asm("mov.b64 {%0, %1}, %2;" : "=f"(f.x), "=f"(f.y) : "l"(v)); return f;
}
#define PKU(out, lo, hi) asm("mov.b64 %0, {%1, %2};" : "=l"(out) : "f"(lo), "f"(hi))

// flag-array grid barrier: one 128B line per flag, PURE relaxed spin + single acquire
static __device__ __forceinline__ void gbar(unsigned tgt) {
    __syncthreads();
    if (threadIdx.x == 0)
        asm volatile("st.release.gpu.global.u32 [%0], %1;"
                     :: "l"(&g_flags[blockIdx.x * FSTR]), "r"(tgt) : "memory");
    if (threadIdx.x < NBLK) {
        const unsigned* fp = &g_flags[threadIdx.x * FSTR];
        unsigned v;
        do {
            asm volatile("ld.relaxed.gpu.global.u32 %0, [%1];" : "=r"(v) : "l"(fp) : "memory");
        } while (v < tgt);
        asm volatile("ld.acquire.gpu.global.u32 %0, [%1];" : "=r"(v) : "l"(fp) : "memory");
    }
    __syncthreads();
}

// ---------------- prep kernels ----------------
__global__ void kt_init(const float* __restrict__ h0) {
    int i = blockIdx.x * 256 + threadIdx.x;
    if (i < NBLK * FSTR) g_flags[i] = 0;
    if (i < BB * HH) {
        int b = i / HH, j = i % HH;
        g_x[b * K2H + j] = 0.f;
        g_x[b * K2H + HH + j] = h0[i];
    }
}

__global__ void kt_gather(const float* __restrict__ emb, const int* __restrict__ ids) {
    int i = blockIdx.x * 256 + threadIdx.x;
    if (i >= TT * BB * EE) return;
    int e = i % EE; int tb = i / EE; int b = tb % BB; int t = tb / BB;
    int tok = ids[b * (TT + 1) + t];
    g_embseq[(t * BB + b) * EE + e] = emb[tok * EE + e];
}

__global__ void kt_prepack_w(const float* __restrict__ Wv) {
    int i = blockIdx.x * 256 + threadIdx.x;
    if (i >= 4000 * 32 * 32) return;
    int lane = i & 31; int tile = i >> 5;
    int kt = tile & 31; int nrow = tile >> 5;
    int gid = lane >> 2, tg = lane & 3;
    const float* p = Wv + (size_t)(nrow * 8 + gid) * HH + kt * 16 + tg * 2;
    uint2 v; v.x = pk_bf2(p[0], p[1]); v.y = pk_bf2(p[8], p[9]);
    g_wswz[i] = v;
}

__global__ void kt_prepack_o() {
    int i = blockIdx.x * 256 + threadIdx.x;
    if (i >= 256 * 32 * 32) return;
    int lane = i & 31; int tile = i >> 5;
    int kt = tile & 31; int mrow = tile >> 5;
    int gid = lane >> 2, tg = lane & 3;
    const float* p = g_oseq + (size_t)(mrow * 16 + gid) * HH + kt * 16 + tg * 2;
    uint4 v;
    v.x = pk_bf2(p[0], p[1]);
    v.y = pk_bf2(p[8 * HH], p[8 * HH + 1]);
    v.z = pk_bf2(p[8], p[9]);
    v.w = pk_bf2(p[8 * HH + 8], p[8 * HH + 9]);
    g_oswz[i] = v;
}

// ---------------- fp32 GEMM: 128x64 tile, 8x4/thread, f32x2 FMA ----------------
__global__ void __launch_bounds__(256) kt_gemm_nt(
    const float* __restrict__ A, int lda, const float* __restrict__ Bm, int ldb,
    float* __restrict__ C, int ldc, int K,
    const float* __restrict__ bias0, const float* __restrict__ bias1)
{
    __shared__ float As[16][132];
    __shared__ float Bs[16][68];
    int tid = threadIdx.x;
    int tx = tid & 15, ty = tid >> 4;
    int m0 = blockIdx.y * 128, n0 = blockIdx.x * 64;
    int ar = tid >> 2, alq = tid & 3;

    ull accp[8][2];
#pragma unroll
    for (int i = 0; i < 8; i++) { accp[i][0] = 0ull; accp[i][1] = 0ull; }

    for (int k0 = 0; k0 < K; k0 += 16) {
        float4 a4a = *(const float4*)(A + (size_t)(m0 + ar) * lda + k0 + alq * 4);
        float4 a4b = *(const float4*)(A + (size_t)(m0 + ar + 64) * lda + k0 + alq * 4);
        float4 b4  = *(const float4*)(Bm + (size_t)(n0 + ar) * ldb + k0 + alq * 4);
        As[alq*4+0][ar] = a4a.x; As[alq*4+1][ar] = a4a.y;
        As[alq*4+2][ar] = a4a.z; As[alq*4+3][ar] = a4a.w;
        As[alq*4+0][ar+64] = a4b.x; As[alq*4+1][ar+64] = a4b.y;
        As[alq*4+2][ar+64] = a4b.z; As[alq*4+3][ar+64] = a4b.w;
        Bs[alq*4+0][ar] = b4.x; Bs[alq*4+1][ar] = b4.y;
        Bs[alq*4+2][ar] = b4.z; Bs[alq*4+3][ar] = b4.w;
        __syncthreads();
#pragma unroll
        for (int kk = 0; kk < 16; kk++) {
            float4 av0 = *(const float4*)&As[kk][ty * 8];
            float4 av1 = *(const float4*)&As[kk][ty * 8 + 4];
            float4 bv  = *(const float4*)&Bs[kk][tx * 4];
            ull b01, b23, s;
            PKU(b01, bv.x, bv.y); PKU(b23, bv.z, bv.w);
            PKU(s, av0.x, av0.x); ffma2(accp[0][0], s, b01); ffma2(accp[0][1], s, b23);
            PKU(s, av0.y, av0.y); ffma2(accp[1][0], s, b01); ffma2(accp[1][1], s, b23);
            PKU(s, av0.z, av0.z); ffma2(accp[2][0], s, b01); ffma2(accp[2][1], s, b23);
            PKU(s, av0.w, av0.w); ffma2(accp[3][0], s, b01); ffma2(accp[3][1], s, b23);
            PKU(s, av1.x, av1.x); ffma2(accp[4][0], s, b01); ffma2(accp[4][1], s, b23);
            PKU(s, av1.y, av1.y); ffma2(accp[5][0], s, b01); ffma2(accp[5][1], s, b23);
            PKU(s, av1.z, av1.z); ffma2(accp[6][0], s, b01); ffma2(accp[6][1], s, b23);
            PKU(s, av1.w, av1.w); ffma2(accp[7][0], s, b01); ffma2(accp[7][1], s, b23);
        }
        __syncthreads();
    }
    float bb[4];
#pragma unroll
    for (int j = 0; j < 4; j++) {
        int n = n0 + tx * 4 + j;
        bb[j] = (bias0 ? bias0[n] : 0.f) + (bias1 ? bias1[n] : 0.f);
    }
#pragma unroll
    for (int i = 0; i < 8; i++) {
        float2 lo = u2f(accp[i][0]), hi = u2f(accp[i][1]);
        float4 o4 = { lo.x + bb[0], lo.y + bb[1], hi.x + bb[2], hi.y + bb[3] };
        *(float4*)(C + (size_t)(m0 + ty * 8 + i) * ldc + n0 + tx * 4) = o4;
    }
}

// ---------------- fused keys+encdec GEMM: A = enc shared, N = 1024 ----------------
// n0 < 512 -> B = W_att (ldb 1024), C = keys ; else B = W_dec (ldb 1536), C = encdec.
__global__ void __launch_bounds__(256) kt_gemm_enc(
    const float* __restrict__ A,
    const float* __restrict__ Watt, const float* __restrict__ Wdec,
    float* __restrict__ keys, float* __restrict__ encdec)
{
    __shared__ float As[16][132];
    __shared__ float Bs[16][68];
    int tid = threadIdx.x;
    int tx = tid & 15, ty = tid >> 4;
    int m0 = blockIdx.y * 128, n0 = blockIdx.x * 64;
    int ar = tid >> 2, alq = tid & 3;

    const float* Bm;
    float* C;
    int ldb, nbase;
    if (n0 < 512) { Bm = Watt; ldb = K2H; C = keys;   nbase = n0; }
    else          { Bm = Wdec; ldb = 1536; C = encdec; nbase = n0 - 512; }

    ull accp[8][2];
#pragma unroll
    for (int i = 0; i < 8; i++) { accp[i][0] = 0ull; accp[i][1] = 0ull; }

    for (int k0 = 0; k0 < K2H; k0 += 16) {
        float4 a4a = *(const float4*)(A + (size_t)(m0 + ar) * K2H + k0 + alq * 4);
        float4 a4b = *(const float4*)(A + (size_t)(m0 + ar + 64) * K2H + k0 + alq * 4);
        float4 b4  = *(const float4*)(Bm + (size_t)(nbase + ar) * ldb + k0 + alq * 4);
        As[alq*4+0][ar] = a4a.x; As[alq*4+1][ar] = a4a.y;
        As[alq*4+2][ar] = a4a.z; As[alq*4+3][ar] = a4a.w;
        As[alq*4+0][ar+64] = a4b.x; As[alq*4+1][ar+64] = a4b.y;
        As[alq*4+2][ar+64] = a4b.z; As[alq*4+3][ar+64] = a4b.w;
        Bs[alq*4+0][ar] = b4.x; Bs[alq*4+1][ar] = b4.y;
        Bs[alq*4+2][ar] = b4.z; Bs[alq*4+3][ar] = b4.w;
        __syncthreads();
#pragma unroll
        for (int kk = 0; kk < 16; kk++) {
            float4 av0 = *(const float4*)&As[kk][ty * 8];
            float4 av1 = *(const float4*)&As[kk][ty * 8 + 4];
            float4 bv  = *(const float4*)&Bs[kk][tx * 4];
            ull b01, b23, s;
            PKU(b01, bv.x, bv.y); PKU(b23, bv.z, bv.w);
            PKU(s, av0.x, av0.x); ffma2(accp[0][0], s, b01); ffma2(accp[0][1], s, b23);
            PKU(s, av0.y, av0.y); ffma2(accp[1][0], s, b01); ffma2(accp[1][1], s, b23);
            PKU(s, av0.z, av0.z); ffma2(accp[2][0], s, b01); ffma2(accp[2][1], s, b23);
            PKU(s, av0.w, av0.w); ffma2(accp[3][0], s, b01); ffma2(accp[3][1], s, b23);
            PKU(s, av1.x, av1.x); ffma2(accp[4][0], s, b01); ffma2(accp[4][1], s, b23);
            PKU(s, av1.y, av1.y); ffma2(accp[5][0], s, b01); ffma2(accp[5][1], s, b23);
            PKU(s, av1.z, av1.z); ffma2(accp[6][0], s, b01); ffma2(accp[6][1], s, b23);
            PKU(s, av1.w, av1.w); ffma2(accp[7][0], s, b01); ffma2(accp[7][1], s, b23);
        }
        __syncthreads();
    }
#pragma unroll
    for (int i = 0; i < 8; i++) {
        float2 lo = u2f(accp[i][0]), hi = u2f(accp[i][1]);
        float4 o4 = { lo.x, lo.y, hi.x, hi.y };
        *(float4*)(C + (size_t)(m0 + ty * 8 + i) * HH + nbase + tx * 4) = o4;
    }
}

// =================== persistent scan (512 threads, slim smem) ===================
// CTA c owns j in [4c, 4c+4). Cell state in smem. Phase A stages x in 2 halves
// (512 floats = 256 ull per row per half; 16 k-splits x 16 ull each).
// smem (bytes): wg f2[16*513]@0 (65664) | wdh f[4*520]@65664 (8320) |
//   stage f[17024]@73984 (68096) | cs f[128]@142080 | mbias f[32]@142592
#define HSTR 514
#define CSTR 516
#define SM_WDH 65664
#define SM_ST  73984
#define SM_CS  142080
#define SM_MB  142592
#define SMEM_SCAN 142720

__global__ void __launch_bounds__(512) kt_scan(
    const int* __restrict__ mask,
    const float* __restrict__ Wih, const float* __restrict__ Whh,
    const float* __restrict__ Wdec, const float* __restrict__ bdec,
    const float* __restrict__ c0)
{
    extern __shared__ char smem[];
    float2* wg    = (float2*)smem;                 // [16][513]
    float*  wdh   = (float*)(smem + SM_WDH);       // [4][520]
    float*  stage = (float*)(smem + SM_ST);        // aliases
    float*  cs    = (float*)(smem + SM_CS);        // [128] cell state
    float*  mbias = (float*)(smem + SM_MB);        // [32]

    int c = blockIdx.x, tid = threadIdx.x;
    int bB = c & 31, qB = c >> 5;

    // stationary gate weights: local row r = type*4 + jj -> global g = type*512 + c*4 + jj
    for (int idx = tid; idx < 16 * 512; idx += 512) {
        int r = idx >> 9, kp = idx & 511;
        int type = r >> 2, jj = r & 3;
        int g = type * 512 + c * 4 + jj;
        int k = kp * 2;
        float a, b2;
        if (k < 512) { a = Wih[g * 768 + 256 + k]; b2 = Wih[g * 768 + 257 + k]; }
        else         { a = Whh[g * 512 + k - 512]; b2 = Whh[g * 512 + k - 511]; }
        wg[r * 513 + kp] = make_float2(a, b2);
    }
    for (int idx = tid; idx < 4 * 512; idx += 512) {
        int jl = idx >> 9, k = idx & 511;
        wdh[jl * 520 + k] = Wdec[(size_t)(c * 4 + jl) * 1536 + 1024 + k];
    }
    if (tid < 32)
        mbias[tid] = (mask[bB * SSRC + qB * 32 + tid] > 0) ? 0.f : -1e9f;
    if (tid < 128)
        cs[tid] = c0[(tid >> 2) * HH + c * 4 + (tid & 3)];

    unsigned tgt = 0;
    __syncthreads();

    int ks = tid >> 5, gt = (tid >> 3) & 3, bt = tid & 7;   // phase A roles

    for (int t = 0; t < TT; t++) {
        // ======== phase A: gates (16 rows x 32 b) + cell update, x staged in halves ====
        {
            float gy0 = 0, gy1 = 0, gy2 = 0, gy3 = 0;
            if (tid < 128) {
                int b = tid >> 2, jj = tid & 3;
                const float* gy = g_gatesy + (size_t)(t * BB + b) * G4 + c * 4 + jj;
                gy0 = gy[0]; gy1 = gy[512]; gy2 = gy[1024]; gy3 = gy[1536];
            }
            ull a00=0,a01=0,a02=0,a03=0, a10=0,a11=0,a12=0,a13=0;
            ull a20=0,a21=0,a22=0,a23=0, a30=0,a31=0,a32=0,a33=0;
            const float2* gx2 = (const float2*)g_x;
#pragma unroll
            for (int half = 0; half < 2; half++) {
                for (int idx = tid; idx < 32 * 256; idx += 512) {
                    int b = idx >> 8, kp = idx & 255;
                    *(float2*)(stage + b * HSTR + kp * 2) = gx2[b * 512 + half * 256 + kp];
                }
                __syncthreads();
                const ull* w0 = (const ull*)(wg + (gt*4+0)*513) + half*256 + ks*16;
                const ull* w1 = (const ull*)(wg + (gt*4+1)*513) + half*256 + ks*16;
                const ull* w2 = (const ull*)(wg + (gt*4+2)*513) + half*256 + ks*16;
                const ull* w3 = (const ull*)(wg + (gt*4+3)*513) + half*256 + ks*16;
                const ull* x0 = (const ull*)(stage + (bt*4+0)*HSTR) + ks*16;
                const ull* x1 = (const ull*)(stage + (bt*4+1)*HSTR) + ks*16;
                const ull* x2 = (const ull*)(stage + (bt*4+2)*HSTR) + ks*16;
                const ull* x3 = (const ull*)(stage + (bt*4+3)*HSTR) + ks*16;
#pragma unroll
                for (int kp = 0; kp < 16; kp++) {
                    ull wa=w0[kp], wb=w1[kp], wc=w2[kp], wd=w3[kp];
                    ull xa=x0[kp], xb=x1[kp], xc=x2[kp], xd=x3[kp];
                    ffma2(a00,wa,xa); ffma2(a01,wa,xb); ffma2(a02,wa,xc); ffma2(a03,wa,xd);
                    ffma2(a10,wb,xa); ffma2(a11,wb,xb); ffma2(a12,wb,xc); ffma2(a13,wb,xd);
                    ffma2(a20,wc,xa); ffma2(a21,wc,xb); ffma2(a22,wc,xc); ffma2(a23,wc,xd);
                    ffma2(a30,wd,xa); ffma2(a31,wd,xb); ffma2(a32,wd,xc); ffma2(a33,wd,xd);
                }
                __syncthreads();
            }
            float* red16 = stage;
            float* gsum  = stage + 8320;
#define RSUM(v) ({ float2 f_ = u2f(v); f_.x + f_.y; })
            {
                float4 r0 = { RSUM(a00), RSUM(a01), RSUM(a02), RSUM(a03) };
                float4 r1 = { RSUM(a10), RSUM(a11), RSUM(a12), RSUM(a13) };
                float4 r2 = { RSUM(a20), RSUM(a21), RSUM(a22), RSUM(a23) };
                float4 r3 = { RSUM(a30), RSUM(a31), RSUM(a32), RSUM(a33) };
                *(float4*)(red16 + ks*520 + (gt*4+0)*32 + bt*4) = r0;
                *(float4*)(red16 + ks*520 + (gt*4+1)*32 + bt*4) = r1;
                *(float4*)(red16 + ks*520 + (gt*4+2)*32 + bt*4) = r2;
                *(float4*)(red16 + ks*520 + (gt*4+3)*32 + bt*4) = r3;
            }
#undef RSUM
            __syncthreads();
            {
                int r = tid >> 5, b = tid & 31;
                float s = 0.f;
#pragma unroll
                for (int q = 0; q < 16; q++) s += red16[q*520 + r*32 + b];
                gsum[r * 33 + b] = s;
            }
            __syncthreads();
            if (tid < 128) {
                int b = tid >> 2, jj = tid & 3;
                float vi = gsum[jj * 33 + b]        + gy0;
                float vf = gsum[(4 + jj) * 33 + b]  + gy1;
                float vg = gsum[(8 + jj) * 33 + b]  + gy2;
                float vo = gsum[(12 + jj) * 33 + b] + gy3;
                float cc = cs[tid];
                float ig = 1.f / (1.f + __expf(-vi));
                float fg = 1.f / (1.f + __expf(-vf));
                float gg = tanhf(vg);
                float og = 1.f / (1.f + __expf(-vo));
                float cn = fg * cc + ig * gg;
                float hn = og * tanhf(cn);
                cs[tid] = cn;
                g_x[b * K2H + HH + c * 4 + jj] = hn;
            }
        }
        gbar(++tgt);

        // ======== phase B: scores + split-softmax + partial ctx (CTA = qB x bB) ========
        {
            float* hs = stage;
            float* sc = stage + 512;
            float* es = stage + 576;
            hs[tid] = g_x[bB * K2H + HH + tid];
            __syncthreads();

            int w = tid >> 5, lane = tid & 31;
            float4 hreg[4];
#pragma unroll
            for (int p = 0; p < 4; p++)
                hreg[p] = *(const float4*)(hs + (lane + p * 32) * 4);
#pragma unroll
            for (int si = 0; si < 2; si++) {
                int sl = w * 2 + si;
                const float4* kp = (const float4*)(g_keys +
                    ((size_t)bB * SSRC + qB * 32 + sl) * HH);
                float acc = 0.f;
#pragma unroll
                for (int p = 0; p < 4; p++) {
                    float4 kv = kp[lane + p * 32];
                    acc += hreg[p].x*kv.x + hreg[p].y*kv.y + hreg[p].z*kv.z + hreg[p].w*kv.w;
                }
#pragma unroll
                for (int off = 16; off; off >>= 1)
                    acc += __shfl_down_sync(0xffffffffu, acc, off);
                if (lane == 0) sc[sl] = acc + mbias[sl];
            }
            __syncthreads();

            if (tid < 32) {
                float v = sc[tid];
                float m = v;
#pragma unroll
                for (int off = 16; off; off >>= 1)
                    m = fmaxf(m, __shfl_xor_sync(0xffffffffu, m, off));
                float e = __expf(v - m);
                es[tid] = e;
                float Z = e;
#pragma unroll
                for (int off = 16; off; off >>= 1)
                    Z += __shfl_xor_sync(0xffffffffu, Z, off);
                if (tid == 0) g_bstats[qB * 32 + bB] = make_float2(m, Z);
            }
            __syncthreads();

            {
                int j = tid;
                const float* ed = g_encdec + ((size_t)bB * SSRC + qB * 32) * HH;
                float p = 0.f;
#pragma unroll 8
                for (int s = 0; s < 32; s++) p += es[s] * ed[(size_t)s * HH + j];
                g_pctx[(qB * 32 + bB) * HH + j] = p;
            }
        }
        gbar(++tgt);

        // ======== phase C: combine + Wdh.h + tanh -> o ========
        {
            for (int idx = tid; idx < 32 * 128; idx += 512) {
                int b = idx >> 7, k4 = idx & 127;
                *(float4*)(stage + b * CSTR + k4 * 4) =
                    *(const float4*)(g_x + b * K2H + HH + k4 * 4);
            }
            __syncthreads();
            float* red2 = stage + 16512;
            {
                int kk = tid >> 7, cell = tid & 127, bC = cell >> 2, jl = cell & 3;
                const float4* wp = (const float4*)(wdh + jl * 520 + kk * 128);
                const float4* hp = (const float4*)(stage + bC * CSTR + kk * 128);
                float acc = 0.f;
#pragma unroll 8
                for (int k4 = 0; k4 < 32; k4++) {
                    float4 wv = wp[k4], hv = hp[k4];
                    acc += wv.x*hv.x + wv.y*hv.y + wv.z*hv.z + wv.w*hv.w;
                }
                red2[kk * 128 + cell] = acc;
            }
            __syncthreads();
            if (tid < 128) {
                float wsum = red2[tid] + red2[128 + tid] + red2[256 + tid] + red2[384 + tid];
                int b = tid >> 2, jl = tid & 3, j = c * 4 + jl;
                float2 st0 = g_bstats[b], st1 = g_bstats[32 + b];
                float2 st2 = g_bstats[64 + b], st3 = g_bstats[96 + b];
                float M = fmaxf(fmaxf(st0.x, st1.x), fmaxf(st2.x, st3.x));
                float w0 = __expf(st0.x - M), w1 = __expf(st1.x - M);
                float w2 = __expf(st2.x - M), w3 = __expf(st3.x - M);
                float den = st0.y*w0 + st1.y*w1 + st2.y*w2 + st3.y*w3;
                float num = w0 * g_pctx[(0*32+b)*HH + j] + w1 * g_pctx[(1*32+b)*HH + j]
                          + w2 * g_pctx[(2*32+b)*HH + j] + w3 * g_pctx[(3*32+b)*HH + j];
                float o = tanhf(num / den + wsum + bdec[j]);
                g_x[b * K2H + j] = o;
                g_oseq[((size_t)b * TT + t) * HH + j] = o;
            }
        }
        gbar(++tgt);
    }
}

// ---------------- vocab GEMM + fused sum-exp partials ----------------
#define MMA16816(d0,d1,d2,d3,A0,A1,A2,A3,B0,B1) \
    asm volatile("mma.sync.aligned.m16n8k16.row.col.f32.bf16.bf16.f32 " \
        "{%0,%1,%2,%3}, {%4,%5,%6,%7}, {%8,%9}, {%0,%1,%2,%3};" \
        : "+f"(d0), "+f"(d1), "+f"(d2), "+f"(d3) \
        : "r"(A0), "r"(A1), "r"(A2), "r"(A3), "r"(B0), "r"(B1))

__global__ void __launch_bounds__(256) kt_vocab_gemm(
    float* __restrict__ out, const float* __restrict__ bvocab)
{
    int nb = blockIdx.x, mb = blockIdx.y;
    int wid = threadIdx.x >> 5, lane = threadIdx.x & 31;
    int wm = wid >> 2, wn = wid & 3;
    int gid = lane >> 2, tg = lane & 3;

    __shared__ float rowsum[128][4];
    if (threadIdx.x < 128) {
#pragma unroll
        for (int w = 0; w < 4; w++) rowsum[threadIdx.x][w] = 0.f;
    }
    __syncthreads();

    float acc[4][4][4];
#pragma unroll
    for (int i = 0; i < 4; i++)
#pragma unroll
        for (int j = 0; j < 4; j++)
#pragma unroll
            for (int r = 0; r < 4; r++) acc[i][j][r] = 0.f;

    int mrow0 = mb * 8 + wm * 4;
    int nrow0 = nb * 16 + wn * 4;

#pragma unroll 2
    for (int kt = 0; kt < 32; kt++) {
        uint4 af[4];
        uint2 bf[4];
#pragma unroll
        for (int mt = 0; mt < 4; mt++)
            af[mt] = g_oswz[(((mrow0 + mt) * 32 + kt) << 5) + lane];
#pragma unroll
        for (int nt = 0; nt < 4; nt++)
            bf[nt] = g_wswz[(((size_t)(nrow0 + nt) * 32 + kt) << 5) + lane];
#pragma unroll
        for (int mt = 0; mt < 4; mt++)
#pragma unroll
            for (int nt = 0; nt < 4; nt++)
                MMA16816(acc[mt][nt][0], acc[mt][nt][1], acc[mt][nt][2], acc[mt][nt][3],
                         af[mt].x, af[mt].y, af[mt].z, af[mt].w, bf[nt].x, bf[nt].y);
    }

    int m_warp = mb * 128 + wm * 64;
    int n_warp = nb * 128 + wn * 32;
#pragma unroll
    for (int mt = 0; mt < 4; mt++) {
        float s0 = 0.f, s1 = 0.f;
#pragma unroll
        for (int nt = 0; nt < 4; nt++) {
            int r = m_warp + mt * 16 + gid;
            int ci = n_warp + nt * 8 + tg * 2;
            float bv0 = bvocab[ci], bv1 = bvocab[ci + 1];
            float v00 = acc[mt][nt][0] + bv0, v01 = acc[mt][nt][1] + bv1;
            float v10 = acc[mt][nt][2] + bv0, v11 = acc[mt][nt][3] + bv1;
            float2 w0 = { v00, v01 }, w1 = { v10, v11 };
            *reinterpret_cast<float2*>(out + (size_t)r * VV + ci) = w0;
            *reinterpret_cast<float2*>(out + (size_t)(r + 8) * VV + ci) = w1;
            s0 += __expf(v00) + __expf(v01);
            s1 += __expf(v10) + __expf(v11);
        }
        s0 += __shfl_xor_sync(0xffffffffu, s0, 1);
        s0 += __shfl_xor_sync(0xffffffffu, s0, 2);
        s1 += __shfl_xor_sync(0xffffffffu, s1, 1);
        s1 += __shfl_xor_sync(0xffffffffu, s1, 2);
        if (tg == 0) {
            rowsum[wm * 64 + mt * 16 + gid][wn] = s0;
            rowsum[wm * 64 + mt * 16 + gid + 8][wn] = s1;
        }
    }
    __syncthreads();
    if (threadIdx.x < 128) {
        float p = rowsum[threadIdx.x][0] + rowsum[threadIdx.x][1]
                + rowsum[threadIdx.x][2] + rowsum[threadIdx.x][3];
        g_partial[(size_t)(mb * 128 + threadIdx.x) * NTILE + nb] = p;
    }
}

__global__ void __launch_bounds__(256) kt_lsfinal(float* __restrict__ out) {
    int row = blockIdx.x, tid = threadIdx.x;
    __shared__ float red[256];
    __shared__ float lse_s;
    float s = 0.f;
    for (int i = tid; i < NTILE; i += 256) s += g_partial[(size_t)row * NTILE + i];
    red[tid] = s;
    __syncthreads();
#pragma unroll
    for (int off = 128; off; off >>= 1) {
        if (tid < off) red[tid] += red[tid + off];
        __syncthreads();
    }
    if (tid == 0) lse_s = logf(red[0]);
    __syncthreads();
    float lse = lse_s;
    float* p = out + (size_t)row * VV;
    for (int i = tid * 4; i < VV; i += 256 * 4) {
        float4 v = *reinterpret_cast<float4*>(p + i);
        v.x -= lse; v.y -= lse; v.z -= lse; v.w -= lse;
        *reinterpret_cast<float4*>(p + i) = v;
    }
}

// ---------------- launch ----------------
extern "C" void kernel_launch(void* const* d_in, const int* in_sizes, int n_in,
                              void* d_out, int out_size)
{
    const float* enc     = (const float*)d_in[0];
    const int*   mask    = (const int*)  d_in[1];
    const int*   ids     = (const int*)  d_in[2];
    const float* h0      = (const float*)d_in[3];
    const float* c0      = (const float*)d_in[4];
    const float* emb     = (const float*)d_in[5];
    const float* W_ih    = (const float*)d_in[6];
    const float* b_ih    = (const float*)d_in[7];
    const float* W_hh    = (const float*)d_in[8];
    const float* b_hh    = (const float*)d_in[9];
    const float* W_att   = (const float*)d_in[10];
    const float* W_dec   = (const float*)d_in[11];
    const float* b_dec   = (const float*)d_in[12];
    const float* W_vocab = (const float*)d_in[13];
    const float* b_vocab = (const float*)d_in[14];
    float* out = (float*)d_out;

    cudaFuncSetAttribute(kt_scan, cudaFuncAttributeMaxDynamicSharedMemorySize, SMEM_SCAN);

    kt_init<<<(BB*HH + 255)/256, 256>>>(h0);
    kt_gather<<<(TT*BB*EE + 255)/256, 256>>>(emb, ids);

    {
        float* keysp; cudaGetSymbolAddress((void**)&keysp, g_keys);
        float* edp;   cudaGetSymbolAddress((void**)&edp, g_encdec);
        float* embp;  cudaGetSymbolAddress((void**)&embp, g_embseq);
        float* gyp;   cudaGetSymbolAddress((void**)&gyp, g_gatesy);
        // fused: keys = enc @ W_att^T  AND  encdec = enc @ W_dec[:, :1024]^T
        kt_gemm_enc<<<dim3(16, 32), 256>>>(enc, W_att, W_dec, keysp, edp);
        // gates_y = emb_seq @ W_ih[:, :256]^T + b_ih + b_hh : M=4096 N=2048 K=256
        kt_gemm_nt<<<dim3(32, 32), 256>>>(embp, EE, W_ih, 768, gyp, G4, EE, b_ih, b_hh);
    }

    kt_scan<<<NBLK, 512, SMEM_SCAN>>>(mask, W_ih, W_hh, W_dec, b_dec, c0);

    kt_prepack_w<<<(4000*32*32 + 255)/256, 256>>>(W_vocab);
    kt_prepack_o<<<(256*32*32 + 255)/256, 256>>>();
    kt_vocab_gemm<<<dim3(NTILE, (BB*TT)/128), 256>>>(out, b_vocab);
    kt_lsfinal<<<BB*TT, 256>>>(out);
}

// round 16
// speedup vs baseline: 1.0411x; 1.0411x over previous
#include <cuda_runtime.h>
#include <cuda_bf16.h>
#include <cstdint>
#include <math.h>

#define BB 32
#define TT 128
#define SSRC 128
#define HH 512
#define EE 256
#define VV 32000
#define K2H 1024
#define G4 2048
#define NBLK 128
#define NSCAN 148   // scan grid: 128 workers + 20 prepack CTAs
#define NTILE 250
#define FSTR 32

typedef unsigned long long ull;

// ---------------- device scratch ----------------
static __device__ float g_keys[BB*SSRC*HH];
static __device__ float g_encdec[BB*SSRC*HH];        // [b][s][j]
static __device__ float g_gatesy[TT*BB*G4];
static __device__ float g_embseq[TT*BB*EE];
static __device__ float g_x[BB*K2H];                 // [o(512), h(512)]
static __device__ float g_pctx[4*BB*HH];             // [q][b][j]
static __device__ float2 g_bstats[4*BB];             // (m, Z)
static __device__ float g_oseq[BB*TT*HH];
static __device__ uint4 g_oswz[256*32*32];
static __device__ uint2 g_wswz[4000*32*32];
static __device__ float g_partial[(size_t)BB*TT*NTILE];
static __device__ unsigned g_flags[NBLK*FSTR];

static __device__ __forceinline__ uint32_t pk_bf2(float lo, float hi) {
    __nv_bfloat16 l = __float2bfloat16(lo), h = __float2bfloat16(hi);
    return (uint32_t)__bfloat16_as_ushort(l) | ((uint32_t)__bfloat16_as_ushort(h) << 16);
}
static __device__ __forceinline__ void ffma2(ull& acc, ull a, ull b) {
    asm volatile("fma.rn.f32x2 %0, %1, %2, %0;" : "+l"(acc) : "l"(a), "l"(b));
}
static __device__ __forceinline__ float2 u2f(ull v) {
    float2 f; asm("mov.b64 {%0, %1}, %2;" : "=f"(f.x), "=f"(f.y) : "l"(v)); return f;
}
#define PKU(out, lo, hi) asm("mov.b64 %0, {%1, %2};" : "=l"(out) : "f"(lo), "f"(hi))

// flag-array grid barrier: one 128B line per flag, relaxed spin + nanosleep backoff
static __device__ __forceinline__ void gbar(unsigned tgt) {
    __syncthreads();
    if (threadIdx.x == 0)
        asm volatile("st.release.gpu.global.u32 [%0], %1;"
                     :: "l"(&g_flags[blockIdx.x * FSTR]), "r"(tgt) : "memory");
    if (threadIdx.x < NBLK) {
        const unsigned* fp = &g_flags[threadIdx.x * FSTR];
        unsigned v;
        asm volatile("ld.relaxed.gpu.global.u32 %0, [%1];" : "=r"(v) : "l"(fp) : "memory");
        while (v < tgt) {
            __nanosleep(32);
            asm volatile("ld.relaxed.gpu.global.u32 %0, [%1];" : "=r"(v) : "l"(fp) : "memory");
        }
        asm volatile("ld.acquire.gpu.global.u32 %0, [%1];" : "=r"(v) : "l"(fp) : "memory");
    }
    __syncthreads();
}

// ---------------- prep kernels ----------------
__global__ void kt_init(const float* __restrict__ h0) {
    int i = blockIdx.x * 256 + threadIdx.x;
    if (i < NBLK * FSTR) g_flags[i] = 0;
    if (i < BB * HH) {
        int b = i / HH, j = i % HH;
        g_x[b * K2H + j] = 0.f;
        g_x[b * K2H + HH + j] = h0[i];
    }
}

__global__ void kt_gather(const float* __restrict__ emb, const int* __restrict__ ids) {
    int i = blockIdx.x * 256 + threadIdx.x;
    if (i >= TT * BB * EE) return;
    int e = i % EE; int tb = i / EE; int b = tb % BB; int t = tb / BB;
    int tok = ids[b * (TT + 1) + t];
    g_embseq[(t * BB + b) * EE + e] = emb[tok * EE + e];
}

__global__ void kt_prepack_o() {
    int i = blockIdx.x * 256 + threadIdx.x;
    if (i >= 256 * 32 * 32) return;
    int lane = i & 31; int tile = i >> 5;
    int kt = tile & 31; int mrow = tile >> 5;
    int gid = lane >> 2, tg = lane & 3;
    const float* p = g_oseq + (size_t)(mrow * 16 + gid) * HH + kt * 16 + tg * 2;
    uint4 v;
    v.x = pk_bf2(p[0], p[1]);
    v.y = pk_bf2(p[8 * HH], p[8 * HH + 1]);
    v.z = pk_bf2(p[8], p[9]);
    v.w = pk_bf2(p[8 * HH + 8], p[8 * HH + 9]);
    g_oswz[i] = v;
}

// ---------------- fp32 GEMM: 128x64 tile, 8x4/thread, f32x2 FMA ----------------
__global__ void __launch_bounds__(256) kt_gemm_nt(
    const float* __restrict__ A, int lda, const float* __restrict__ Bm, int ldb,
    float* __restrict__ C, int ldc, int K,
    const float* __restrict__ bias0, const float* __restrict__ bias1)
{
    __shared__ float As[16][132];
    __shared__ float Bs[16][68];
    int tid = threadIdx.x;
    int tx = tid & 15, ty = tid >> 4;
    int m0 = blockIdx.y * 128, n0 = blockIdx.x * 64;
    int ar = tid >> 2, alq = tid & 3;

    ull accp[8][2];
#pragma unroll
    for (int i = 0; i < 8; i++) { accp[i][0] = 0ull; accp[i][1] = 0ull; }

    for (int k0 = 0; k0 < K; k0 += 16) {
        float4 a4a = *(const float4*)(A + (size_t)(m0 + ar) * lda + k0 + alq * 4);
        float4 a4b = *(const float4*)(A + (size_t)(m0 + ar + 64) * lda + k0 + alq * 4);
        float4 b4  = *(const float4*)(Bm + (size_t)(n0 + ar) * ldb + k0 + alq * 4);
        As[alq*4+0][ar] = a4a.x; As[alq*4+1][ar] = a4a.y;
        As[alq*4+2][ar] = a4a.z; As[alq*4+3][ar] = a4a.w;
        As[alq*4+0][ar+64] = a4b.x; As[alq*4+1][ar+64] = a4b.y;
        As[alq*4+2][ar+64] = a4b.z; As[alq*4+3][ar+64] = a4b.w;
        Bs[alq*4+0][ar] = b4.x; Bs[alq*4+1][ar] = b4.y;
        Bs[alq*4+2][ar] = b4.z; Bs[alq*4+3][ar] = b4.w;
        __syncthreads();
#pragma unroll
        for (int kk = 0; kk < 16; kk++) {
            float4 av0 = *(const float4*)&As[kk][ty * 8];
            float4 av1 = *(const float4*)&As[kk][ty * 8 + 4];
            float4 bv  = *(const float4*)&Bs[kk][tx * 4];
            ull b01, b23, s;
            PKU(b01, bv.x, bv.y); PKU(b23, bv.z, bv.w);
            PKU(s, av0.x, av0.x); ffma2(accp[0][0], s, b01); ffma2(accp[0][1], s, b23);
            PKU(s, av0.y, av0.y); ffma2(accp[1][0], s, b01); ffma2(accp[1][1], s, b23);
            PKU(s, av0.z, av0.z); ffma2(accp[2][0], s, b01); ffma2(accp[2][1], s, b23);
            PKU(s, av0.w, av0.w); ffma2(accp[3][0], s, b01); ffma2(accp[3][1], s, b23);
            PKU(s, av1.x, av1.x); ffma2(accp[4][0], s, b01); ffma2(accp[4][1], s, b23);
            PKU(s, av1.y, av1.y); ffma2(accp[5][0], s, b01); ffma2(accp[5][1], s, b23);
            PKU(s, av1.z, av1.z); ffma2(accp[6][0], s, b01); ffma2(accp[6][1], s, b23);
            PKU(s, av1.w, av1.w); ffma2(accp[7][0], s, b01); ffma2(accp[7][1], s, b23);
        }
        __syncthreads();
    }
    float bb[4];
#pragma unroll
    for (int j = 0; j < 4; j++) {
        int n = n0 + tx * 4 + j;
        bb[j] = (bias0 ? bias0[n] : 0.f) + (bias1 ? bias1[n] : 0.f);
    }
#pragma unroll
    for (int i = 0; i < 8; i++) {
        float2 lo = u2f(accp[i][0]), hi = u2f(accp[i][1]);
        float4 o4 = { lo.x + bb[0], lo.y + bb[1], hi.x + bb[2], hi.y + bb[3] };
        *(float4*)(C + (size_t)(m0 + ty * 8 + i) * ldc + n0 + tx * 4) = o4;
    }
}

// ---------------- fused keys+encdec GEMM: A = enc shared, N = 1024 ----------------
__global__ void __launch_bounds__(256) kt_gemm_enc(
    const float* __restrict__ A,
    const float* __restrict__ Watt, const float* __restrict__ Wdec,
    float* __restrict__ keys, float* __restrict__ encdec)
{
    __shared__ float As[16][132];
    __shared__ float Bs[16][68];
    int tid = threadIdx.x;
    int tx = tid & 15, ty = tid >> 4;
    int m0 = blockIdx.y * 128, n0 = blockIdx.x * 64;
    int ar = tid >> 2, alq = tid & 3;

    const float* Bm;
    float* C;
    int ldb, nbase;
    if (n0 < 512) { Bm = Watt; ldb = K2H; C = keys;   nbase = n0; }
    else          { Bm = Wdec; ldb = 1536; C = encdec; nbase = n0 - 512; }

    ull accp[8][2];
#pragma unroll
    for (int i = 0; i < 8; i++) { accp[i][0] = 0ull; accp[i][1] = 0ull; }

    for (int k0 = 0; k0 < K2H; k0 += 16) {
        float4 a4a = *(const float4*)(A + (size_t)(m0 + ar) * K2H + k0 + alq * 4);
        float4 a4b = *(const float4*)(A + (size_t)(m0 + ar + 64) * K2H + k0 + alq * 4);
        float4 b4  = *(const float4*)(Bm + (size_t)(nbase + ar) * ldb + k0 + alq * 4);
        As[alq*4+0][ar] = a4a.x; As[alq*4+1][ar] = a4a.y;
        As[alq*4+2][ar] = a4a.z; As[alq*4+3][ar] = a4a.w;
        As[alq*4+0][ar+64] = a4b.x; As[alq*4+1][ar+64] = a4b.y;
        As[alq*4+2][ar+64] = a4b.z; As[alq*4+3][ar+64] = a4b.w;
        Bs[alq*4+0][ar] = b4.x; Bs[alq*4+1][ar] = b4.y;
        Bs[alq*4+2][ar] = b4.z; Bs[alq*4+3][ar] = b4.w;
        __syncthreads();
#pragma unroll
        for (int kk = 0; kk < 16; kk++) {
            float4 av0 = *(const float4*)&As[kk][ty * 8];
            float4 av1 = *(const float4*)&As[kk][ty * 8 + 4];
            float4 bv  = *(const float4*)&Bs[kk][tx * 4];
            ull b01, b23, s;
            PKU(b01, bv.x, bv.y); PKU(b23, bv.z, bv.w);
            PKU(s, av0.x, av0.x); ffma2(accp[0][0], s, b01); ffma2(accp[0][1], s, b23);
            PKU(s, av0.y, av0.y); ffma2(accp[1][0], s, b01); ffma2(accp[1][1], s, b23);
            PKU(s, av0.z, av0.z); ffma2(accp[2][0], s, b01); ffma2(accp[2][1], s, b23);
            PKU(s, av0.w, av0.w); ffma2(accp[3][0], s, b01); ffma2(accp[3][1], s, b23);
            PKU(s, av1.x, av1.x); ffma2(accp[4][0], s, b01); ffma2(accp[4][1], s, b23);
            PKU(s, av1.y, av1.y); ffma2(accp[5][0], s, b01); ffma2(accp[5][1], s, b23);
            PKU(s, av1.z, av1.z); ffma2(accp[6][0], s, b01); ffma2(accp[6][1], s, b23);
            PKU(s, av1.w, av1.w); ffma2(accp[7][0], s, b01); ffma2(accp[7][1], s, b23);
        }
        __syncthreads();
    }
#pragma unroll
    for (int i = 0; i < 8; i++) {
        float2 lo = u2f(accp[i][0]), hi = u2f(accp[i][1]);
        float4 o4 = { lo.x, lo.y, hi.x, hi.y };
        *(float4*)(C + (size_t)(m0 + ty * 8 + i) * HH + nbase + tx * 4) = o4;
    }
}

// =================== persistent scan (512 threads, slim smem) ===================
// Grid = 148: CTAs [0,128) run the scan; CTAs [128,148) prepack W_vocab (overlap).
// smem (bytes): wg f2[16*513]@0 (65664) | wdh f[4*520]@65664 (8320) |
//   stage f[17024]@73984 (68096) | cs f[128]@142080 | mbias f[32]@142592
#define HSTR 514
#define CSTR 516
#define SM_WDH 65664
#define SM_ST  73984
#define SM_CS  142080
#define SM_MB  142592
#define SMEM_SCAN 142720

__global__ void __launch_bounds__(512) kt_scan(
    const int* __restrict__ mask,
    const float* __restrict__ Wih, const float* __restrict__ Whh,
    const float* __restrict__ Wdec, const float* __restrict__ bdec,
    const float* __restrict__ c0, const float* __restrict__ Wv)
{
    int c = blockIdx.x, tid = threadIdx.x;

    // ---- overlap CTAs: prepack W_vocab fragments while workers scan ----
    if (c >= NBLK) {
        int pc = c - NBLK;                       // 0..19
        const int TOTAL = 4000 * 32 * 32;        // 4.096M fragments
        int per = (TOTAL + 19) / 20;             // 204800
        int lo = pc * per;
        int hi = min(lo + per, TOTAL);
        for (int i = lo + tid; i < hi; i += 512) {
            int lane = i & 31; int tile = i >> 5;
            int kt = tile & 31; int nrow = tile >> 5;
            int gid = lane >> 2, tg = lane & 3;
            const float* p = Wv + (size_t)(nrow * 8 + gid) * HH + kt * 16 + tg * 2;
            uint2 v; v.x = pk_bf2(p[0], p[1]); v.y = pk_bf2(p[8], p[9]);
            g_wswz[i] = v;
        }
        return;
    }

    extern __shared__ char smem[];
    float2* wg    = (float2*)smem;                 // [16][513]
    float*  wdh   = (float*)(smem + SM_WDH);       // [4][520]
    float*  stage = (float*)(smem + SM_ST);        // aliases
    float*  cs    = (float*)(smem + SM_CS);        // [128] cell state
    float*  mbias = (float*)(smem + SM_MB);        // [32]

    int bB = c & 31, qB = c >> 5;

    // stationary gate weights: local row r = type*4 + jj -> global g = type*512 + c*4 + jj
    for (int idx = tid; idx < 16 * 512; idx += 512) {
        int r = idx >> 9, kp = idx & 511;
        int type = r >> 2, jj = r & 3;
        int g = type * 512 + c * 4 + jj;
        int k = kp * 2;
        float a, b2;
        if (k < 512) { a = Wih[g * 768 + 256 + k]; b2 = Wih[g * 768 + 257 + k]; }
        else         { a = Whh[g * 512 + k - 512]; b2 = Whh[g * 512 + k - 511]; }
        wg[r * 513 + kp] = make_float2(a, b2);
    }
    for (int idx = tid; idx < 4 * 512; idx += 512) {
        int jl = idx >> 9, k = idx & 511;
        wdh[jl * 520 + k] = Wdec[(size_t)(c * 4 + jl) * 1536 + 1024 + k];
    }
    if (tid < 32)
        mbias[tid] = (mask[bB * SSRC + qB * 32 + tid] > 0) ? 0.f : -1e9f;
    if (tid < 128)
        cs[tid] = c0[(tid >> 2) * HH + c * 4 + (tid & 3)];

    unsigned tgt = 0;
    __syncthreads();

    int ks = tid >> 5, gt = (tid >> 3) & 3, bt = tid & 7;   // phase A roles

    for (int t = 0; t < TT; t++) {
        // ======== phase A: gates (16 rows x 32 b) + cell update, x staged in halves ====
        {
            float gy0 = 0, gy1 = 0, gy2 = 0, gy3 = 0;
            if (tid < 128) {
                int b = tid >> 2, jj = tid & 3;
                const float* gy = g_gatesy + (size_t)(t * BB + b) * G4 + c * 4 + jj;
                gy0 = gy[0]; gy1 = gy[512]; gy2 = gy[1024]; gy3 = gy[1536];
            }
            ull a00=0,a01=0,a02=0,a03=0, a10=0,a11=0,a12=0,a13=0;
            ull a20=0,a21=0,a22=0,a23=0, a30=0,a31=0,a32=0,a33=0;
            const float2* gx2 = (const float2*)g_x;
#pragma unroll
            for (int half = 0; half < 2; half++) {
                for (int idx = tid; idx < 32 * 256; idx += 512) {
                    int b = idx >> 8, kp = idx & 255;
                    *(float2*)(stage + b * HSTR + kp * 2) = gx2[b * 512 + half * 256 + kp];
                }
                __syncthreads();
                const ull* w0 = (const ull*)(wg + (gt*4+0)*513) + half*256 + ks*16;
                const ull* w1 = (const ull*)(wg + (gt*4+1)*513) + half*256 + ks*16;
                const ull* w2 = (const ull*)(wg + (gt*4+2)*513) + half*256 + ks*16;
                const ull* w3 = (const ull*)(wg + (gt*4+3)*513) + half*256 + ks*16;
                const ull* x0 = (const ull*)(stage + (bt*4+0)*HSTR) + ks*16;
                const ull* x1 = (const ull*)(stage + (bt*4+1)*HSTR) + ks*16;
                const ull* x2 = (const ull*)(stage + (bt*4+2)*HSTR) + ks*16;
                const ull* x3 = (const ull*)(stage + (bt*4+3)*HSTR) + ks*16;
#pragma unroll
                for (int kp = 0; kp < 16; kp++) {
                    ull wa=w0[kp], wb=w1[kp], wc=w2[kp], wd=w3[kp];
                    ull xa=x0[kp], xb=x1[kp], xc=x2[kp], xd=x3[kp];
                    ffma2(a00,wa,xa); ffma2(a01,wa,xb); ffma2(a02,wa,xc); ffma2(a03,wa,xd);
                    ffma2(a10,wb,xa); ffma2(a11,wb,xb); ffma2(a12,wb,xc); ffma2(a13,wb,xd);
                    ffma2(a20,wc,xa); ffma2(a21,wc,xb); ffma2(a22,wc,xc); ffma2(a23,wc,xd);
                    ffma2(a30,wd,xa); ffma2(a31,wd,xb); ffma2(a32,wd,xc); ffma2(a33,wd,xd);
                }
                __syncthreads();
            }
            float* red16 = stage;
            float* gsum  = stage + 8320;
#define RSUM(v) ({ float2 f_ = u2f(v); f_.x + f_.y; })
            {
                float4 r0 = { RSUM(a00), RSUM(a01), RSUM(a02), RSUM(a03) };
                float4 r1 = { RSUM(a10), RSUM(a11), RSUM(a12), RSUM(a13) };
                float4 r2 = { RSUM(a20), RSUM(a21), RSUM(a22), RSUM(a23) };
                float4 r3 = { RSUM(a30), RSUM(a31), RSUM(a32), RSUM(a33) };
                *(float4*)(red16 + ks*520 + (gt*4+0)*32 + bt*4) = r0;
                *(float4*)(red16 + ks*520 + (gt*4+1)*32 + bt*4) = r1;
                *(float4*)(red16 + ks*520 + (gt*4+2)*32 + bt*4) = r2;
                *(float4*)(red16 + ks*520 + (gt*4+3)*32 + bt*4) = r3;
            }
#undef RSUM
            __syncthreads();
            {
                int r = tid >> 5, b = tid & 31;
                float s = 0.f;
#pragma unroll
                for (int q = 0; q < 16; q++) s += red16[q*520 + r*32 + b];
                gsum[r * 33 + b] = s;
            }
            __syncthreads();
            if (tid < 128) {
                int b = tid >> 2, jj = tid & 3;
                float vi = gsum[jj * 33 + b]        + gy0;
                float vf = gsum[(4 + jj) * 33 + b]  + gy1;
                float vg = gsum[(8 + jj) * 33 + b]  + gy2;
                float vo = gsum[(12 + jj) * 33 + b] + gy3;
                float cc = cs[tid];
                float ig = 1.f / (1.f + __expf(-vi));
                float fg = 1.f / (1.f + __expf(-vf));
                float gg = tanhf(vg);
                float og = 1.f / (1.f + __expf(-vo));
                float cn = fg * cc + ig * gg;
                float hn = og * tanhf(cn);
                cs[tid] = cn;
                g_x[b * K2H + HH + c * 4 + jj] = hn;
            }
        }
        gbar(++tgt);

        // ======== phase B: scores + split-softmax + partial ctx (CTA = qB x bB) ========
        {
            float* hs = stage;
            float* sc = stage + 512;
            float* es = stage + 576;
            hs[tid] = g_x[bB * K2H + HH + tid];
            __syncthreads();

            int w = tid >> 5, lane = tid & 31;
            float4 hreg[4];
#pragma unroll
            for (int p = 0; p < 4; p++)
                hreg[p] = *(const float4*)(hs + (lane + p * 32) * 4);
#pragma unroll
            for (int si = 0; si < 2; si++) {
                int sl = w * 2 + si;
                const float4* kp = (const float4*)(g_keys +
                    ((size_t)bB * SSRC + qB * 32 + sl) * HH);
                float acc = 0.f;
#pragma unroll
                for (int p = 0; p < 4; p++) {
                    float4 kv = kp[lane + p * 32];
                    acc += hreg[p].x*kv.x + hreg[p].y*kv.y + hreg[p].z*kv.z + hreg[p].w*kv.w;
                }
#pragma unroll
                for (int off = 16; off; off >>= 1)
                    acc += __shfl_down_sync(0xffffffffu, acc, off);
                if (lane == 0) sc[sl] = acc + mbias[sl];
            }
            __syncthreads();

            if (tid < 32) {
                float v = sc[tid];
                float m = v;
#pragma unroll
                for (int off = 16; off; off >>= 1)
                    m = fmaxf(m, __shfl_xor_sync(0xffffffffu, m, off));
                float e = __expf(v - m);
                es[tid] = e;
                float Z = e;
#pragma unroll
                for (int off = 16; off; off >>= 1)
                    Z += __shfl_xor_sync(0xffffffffu, Z, off);
                if (tid == 0) g_bstats[qB * 32 + bB] = make_float2(m, Z);
            }
            __syncthreads();

            {
                int j = tid;
                const float* ed = g_encdec + ((size_t)bB * SSRC + qB * 32) * HH;
                float p = 0.f;
#pragma unroll 8
                for (int s = 0; s < 32; s++) p += es[s] * ed[(size_t)s * HH + j];
                g_pctx[(qB * 32 + bB) * HH + j] = p;
            }
        }
        gbar(++tgt);

        // ======== phase C: combine + Wdh.h + tanh -> o ========
        {
            for (int idx = tid; idx < 32 * 128; idx += 512) {
                int b = idx >> 7, k4 = idx & 127;
                *(float4*)(stage + b * CSTR + k4 * 4) =
                    *(const float4*)(g_x + b * K2H + HH + k4 * 4);
            }
            __syncthreads();
            float* red2 = stage + 16512;
            {
                int kk = tid >> 7, cell = tid & 127, bC = cell >> 2, jl = cell & 3;
                const float4* wp = (const float4*)(wdh + jl * 520 + kk * 128);
                const float4* hp = (const float4*)(stage + bC * CSTR + kk * 128);
                float acc = 0.f;
#pragma unroll 8
                for (int k4 = 0; k4 < 32; k4++) {
                    float4 wv = wp[k4], hv = hp[k4];
                    acc += wv.x*hv.x + wv.y*hv.y + wv.z*hv.z + wv.w*hv.w;
                }
                red2[kk * 128 + cell] = acc;
            }
            __syncthreads();
            if (tid < 128) {
                float wsum = red2[tid] + red2[128 + tid] + red2[256 + tid] + red2[384 + tid];
                int b = tid >> 2, jl = tid & 3, j = c * 4 + jl;
                float2 st0 = g_bstats[b], st1 = g_bstats[32 + b];
                float2 st2 = g_bstats[64 + b], st3 = g_bstats[96 + b];
                float M = fmaxf(fmaxf(st0.x, st1.x), fmaxf(st2.x, st3.x));
                float w0 = __expf(st0.x - M), w1 = __expf(st1.x - M);
                float w2 = __expf(st2.x - M), w3 = __expf(st3.x - M);
                float den = st0.y*w0 + st1.y*w1 + st2.y*w2 + st3.y*w3;
                float num = w0 * g_pctx[(0*32+b)*HH + j] + w1 * g_pctx[(1*32+b)*HH + j]
                          + w2 * g_pctx[(2*32+b)*HH + j] + w3 * g_pctx[(3*32+b)*HH + j];
                float o = tanhf(num / den + wsum + bdec[j]);
                g_x[b * K2H + j] = o;
                g_oseq[((size_t)b * TT + t) * HH + j] = o;
            }
        }
        gbar(++tgt);
    }
}

// ---------------- vocab GEMM + fused sum-exp partials ----------------
#define MMA16816(d0,d1,d2,d3,A0,A1,A2,A3,B0,B1) \
    asm volatile("mma.sync.aligned.m16n8k16.row.col.f32.bf16.bf16.f32 " \
        "{%0,%1,%2,%3}, {%4,%5,%6,%7}, {%8,%9}, {%0,%1,%2,%3};" \
        : "+f"(d0), "+f"(d1), "+f"(d2), "+f"(d3) \
        : "r"(A0), "r"(A1), "r"(A2), "r"(A3), "r"(B0), "r"(B1))

__global__ void __launch_bounds__(256) kt_vocab_gemm(
    float* __restrict__ out, const float* __restrict__ bvocab)
{
    int nb = blockIdx.x, mb = blockIdx.y;
    int wid = threadIdx.x >> 5, lane = threadIdx.x & 31;
    int wm = wid >> 2, wn = wid & 3;
    int gid = lane >> 2, tg = lane & 3;

    __shared__ float rowsum[128][4];
    if (threadIdx.x < 128) {
#pragma unroll
        for (int w = 0; w < 4; w++) rowsum[threadIdx.x][w] = 0.f;
    }
    __syncthreads();

    float acc[4][4][4];
#pragma unroll
    for (int i = 0; i < 4; i++)
#pragma unroll
        for (int j = 0; j < 4; j++)
#pragma unroll
            for (int r = 0; r < 4; r++) acc[i][j][r] = 0.f;

    int mrow0 = mb * 8 + wm * 4;
    int nrow0 = nb * 16 + wn * 4;

#pragma unroll 2
    for (int kt = 0; kt < 32; kt++) {
        uint4 af[4];
        uint2 bf[4];
#pragma unroll
        for (int mt = 0; mt < 4; mt++)
            af[mt] = g_oswz[(((mrow0 + mt) * 32 + kt) << 5) + lane];
#pragma unroll
        for (int nt = 0; nt < 4; nt++)
            bf[nt] = g_wswz[(((size_t)(nrow0 + nt) * 32 + kt) << 5) + lane];
#pragma unroll
        for (int mt = 0; mt < 4; mt++)
#pragma unroll
            for (int nt = 0; nt < 4; nt++)
                MMA16816(acc[mt][nt][0], acc[mt][nt][1], acc[mt][nt][2], acc[mt][nt][3],
                         af[mt].x, af[mt].y, af[mt].z, af[mt].w, bf[nt].x, bf[nt].y);
    }

    int m_warp = mb * 128 + wm * 64;
    int n_warp = nb * 128 + wn * 32;
#pragma unroll
    for (int mt = 0; mt < 4; mt++) {
        float s0 = 0.f, s1 = 0.f;
#pragma unroll
        for (int nt = 0; nt < 4; nt++) {
            int r = m_warp + mt * 16 + gid;
            int ci = n_warp + nt * 8 + tg * 2;
            float bv0 = bvocab[ci], bv1 = bvocab[ci + 1];
            float v00 = acc[mt][nt][0] + bv0, v01 = acc[mt][nt][1] + bv1;
            float v10 = acc[mt][nt][2] + bv0, v11 = acc[mt][nt][3] + bv1;
            float2 w0 = { v00, v01 }, w1 = { v10, v11 };
            *reinterpret_cast<float2*>(out + (size_t)r * VV + ci) = w0;
            *reinterpret_cast<float2*>(out + (size_t)(r + 8) * VV + ci) = w1;
            s0 += __expf(v00) + __expf(v01);
            s1 += __expf(v10) + __expf(v11);
        }
        s0 += __shfl_xor_sync(0xffffffffu, s0, 1);
        s0 += __shfl_xor_sync(0xffffffffu, s0, 2);
        s1 += __shfl_xor_sync(0xffffffffu, s1, 1);
        s1 += __shfl_xor_sync(0xffffffffu, s1, 2);
        if (tg == 0) {
            rowsum[wm * 64 + mt * 16 + gid][wn] = s0;
            rowsum[wm * 64 + mt * 16 + gid + 8][wn] = s1;
        }
    }
    __syncthreads();
    if (threadIdx.x < 128) {
        float p = rowsum[threadIdx.x][0] + rowsum[threadIdx.x][1]
                + rowsum[threadIdx.x][2] + rowsum[threadIdx.x][3];
        g_partial[(size_t)(mb * 128 + threadIdx.x) * NTILE + nb] = p;
    }
}

__global__ void __launch_bounds__(256) kt_lsfinal(float* __restrict__ out) {
    int row = blockIdx.x, tid = threadIdx.x;
    __shared__ float red[256];
    __shared__ float lse_s;
    float s = 0.f;
    for (int i = tid; i < NTILE; i += 256) s += g_partial[(size_t)row * NTILE + i];
    red[tid] = s;
    __syncthreads();
#pragma unroll
    for (int off = 128; off; off >>= 1) {
        if (tid < off) red[tid] += red[tid + off];
        __syncthreads();
    }
    if (tid == 0) lse_s = logf(red[0]);
    __syncthreads();
    float lse = lse_s;
    float* p = out + (size_t)row * VV;
    for (int i = tid * 4; i < VV; i += 256 * 4) {
        float4 v = *reinterpret_cast<float4*>(p + i);
        v.x -= lse; v.y -= lse; v.z -= lse; v.w -= lse;
        *reinterpret_cast<float4*>(p + i) = v;
    }
}

// ---------------- launch ----------------
extern "C" void kernel_launch(void* const* d_in, const int* in_sizes, int n_in,
                              void* d_out, int out_size)
{
    const float* enc     = (const float*)d_in[0];
    const int*   mask    = (const int*)  d_in[1];
    const int*   ids     = (const int*)  d_in[2];
    const float* h0      = (const float*)d_in[3];
    const float* c0      = (const float*)d_in[4];
    const float* emb     = (const float*)d_in[5];
    const float* W_ih    = (const float*)d_in[6];
    const float* b_ih    = (const float*)d_in[7];
    const float* W_hh    = (const float*)d_in[8];
    const float* b_hh    = (const float*)d_in[9];
    const float* W_att   = (const float*)d_in[10];
    const float* W_dec   = (const float*)d_in[11];
    const float* b_dec   = (const float*)d_in[12];
    const float* W_vocab = (const float*)d_in[13];
    const float* b_vocab = (const float*)d_in[14];
    float* out = (float*)d_out;

    cudaFuncSetAttribute(kt_scan, cudaFuncAttributeMaxDynamicSharedMemorySize, SMEM_SCAN);

    kt_init<<<(BB*HH + 255)/256, 256>>>(h0);
    kt_gather<<<(TT*BB*EE + 255)/256, 256>>>(emb, ids);

    {
        float* keysp; cudaGetSymbolAddress((void**)&keysp, g_keys);
        float* edp;   cudaGetSymbolAddress((void**)&edp, g_encdec);
        float* embp;  cudaGetSymbolAddress((void**)&embp, g_embseq);
        float* gyp;   cudaGetSymbolAddress((void**)&gyp, g_gatesy);
        // fused: keys = enc @ W_att^T  AND  encdec = enc @ W_dec[:, :1024]^T
        kt_gemm_enc<<<dim3(16, 32), 256>>>(enc, W_att, W_dec, keysp, edp);
        // gates_y = emb_seq @ W_ih[:, :256]^T + b_ih + b_hh : M=4096 N=2048 K=256
        kt_gemm_nt<<<dim3(32, 32), 256>>>(embp, EE, W_ih, 768, gyp, G4, EE, b_ih, b_hh);
    }

    // scan (128 worker CTAs) + W_vocab prepack (20 overlap CTAs), one launch
    kt_scan<<<NSCAN, 512, SMEM_SCAN>>>(mask, W_ih, W_hh, W_dec, b_dec, c0, W_vocab);

    kt_prepack_o<<<(256*32*32 + 255)/256, 256>>>();
    kt_vocab_gemm<<<dim3(NTILE, (BB*TT)/128), 256>>>(out, b_vocab);
    kt_lsfinal<<<BB*TT, 256>>>(out);
}

// round 17
// speedup vs baseline: 1.0469x; 1.0056x over previous
#include <cuda_runtime.h>
#include <cuda_bf16.h>
#include <cstdint>
#include <math.h>

#define BB 32
#define TT 128
#define SSRC 128
#define HH 512
#define EE 256
#define VV 32000
#define K2H 1024
#define G4 2048
#define NBLK 128
#define NSCAN 148   // scan grid: 128 workers + 20 prepack CTAs
#define NTILE 250
#define FSTR 32

typedef unsigned long long ull;

// ---------------- device scratch ----------------
static __device__ float g_keys[BB*SSRC*HH];
static __device__ float g_encdec[BB*SSRC*HH];        // [b][s][j]
static __device__ float g_gatesy[TT*BB*G4];
static __device__ float g_embseq[TT*BB*EE];
static __device__ float g_x[BB*K2H];                 // [o(512), h(512)]
static __device__ float g_pctx[4*BB*HH];             // [q][b][j]
static __device__ float2 g_bstats[4*BB];             // (m, Z)
static __device__ float g_oseq[BB*TT*HH];
static __device__ uint4 g_oswz[256*32*32];
static __device__ uint2 g_wswz[4000*32*32];
static __device__ float g_partial[(size_t)BB*TT*NTILE];
static __device__ unsigned g_flags[NBLK*FSTR];

static __device__ __forceinline__ uint32_t pk_bf2(float lo, float hi) {
    __nv_bfloat16 l = __float2bfloat16(lo), h = __float2bfloat16(hi);
    return (uint32_t)__bfloat16_as_ushort(l) | ((uint32_t)__bfloat16_as_ushort(h) << 16);
}
static __device__ __forceinline__ void ffma2(ull& acc, ull a, ull b) {
    asm volatile("fma.rn.f32x2 %0, %1, %2, %0;" : "+l"(acc) : "l"(a), "l"(b));
}
static __device__ __forceinline__ float2 u2f(ull v) {
    float2 f; asm("mov.b64 {%0, %1}, %2;" : "=f"(f.x), "=f"(f.y) : "l"(v)); return f;
}
#define PKU(out, lo, hi) asm("mov.b64 %0, {%1, %2};" : "=l"(out) : "f"(lo), "f"(hi))

// flag-array grid barrier: one 128B line per flag, relaxed spin + nanosleep backoff
static __device__ __forceinline__ void gbar(unsigned tgt) {
    __syncthreads();
    if (threadIdx.x == 0)
        asm volatile("st.release.gpu.global.u32 [%0], %1;"
                     :: "l"(&g_flags[blockIdx.x * FSTR]), "r"(tgt) : "memory");
    if (threadIdx.x < NBLK) {
        const unsigned* fp = &g_flags[threadIdx.x * FSTR];
        unsigned v;
        asm volatile("ld.relaxed.gpu.global.u32 %0, [%1];" : "=r"(v) : "l"(fp) : "memory");
        while (v < tgt) {
            __nanosleep(32);
            asm volatile("ld.relaxed.gpu.global.u32 %0, [%1];" : "=r"(v) : "l"(fp) : "memory");
        }
        asm volatile("ld.acquire.gpu.global.u32 %0, [%1];" : "=r"(v) : "l"(fp) : "memory");
    }
    __syncthreads();
}

// ---------------- prep kernels ----------------
__global__ void kt_init(const float* __restrict__ h0) {
    int i = blockIdx.x * 256 + threadIdx.x;
    if (i < NBLK * FSTR) g_flags[i] = 0;
    if (i < BB * HH) {
        int b = i / HH, j = i % HH;
        g_x[b * K2H + j] = 0.f;
        g_x[b * K2H + HH + j] = h0[i];
    }
}

__global__ void kt_gather(const float* __restrict__ emb, const int* __restrict__ ids) {
    int i = blockIdx.x * 256 + threadIdx.x;
    if (i >= TT * BB * EE) return;
    int e = i % EE; int tb = i / EE; int b = tb % BB; int t = tb / BB;
    int tok = ids[b * (TT + 1) + t];
    g_embseq[(t * BB + b) * EE + e] = emb[tok * EE + e];
}

__global__ void kt_prepack_o() {
    int i = blockIdx.x * 256 + threadIdx.x;
    if (i >= 256 * 32 * 32) return;
    int lane = i & 31; int tile = i >> 5;
    int kt = tile & 31; int mrow = tile >> 5;
    int gid = lane >> 2, tg = lane & 3;
    const float* p = g_oseq + (size_t)(mrow * 16 + gid) * HH + kt * 16 + tg * 2;
    uint4 v;
    v.x = pk_bf2(p[0], p[1]);
    v.y = pk_bf2(p[8 * HH], p[8 * HH + 1]);
    v.z = pk_bf2(p[8], p[9]);
    v.w = pk_bf2(p[8 * HH + 8], p[8 * HH + 9]);
    g_oswz[i] = v;
}

// ---------------- fp32 GEMM: 128x64 tile, 8x4/thread, f32x2 FMA ----------------
__global__ void __launch_bounds__(256) kt_gemm_nt(
    const float* __restrict__ A, int lda, const float* __restrict__ Bm, int ldb,
    float* __restrict__ C, int ldc, int K,
    const float* __restrict__ bias0, const float* __restrict__ bias1)
{
    __shared__ float As[16][132];
    __shared__ float Bs[16][68];
    int tid = threadIdx.x;
    int tx = tid & 15, ty = tid >> 4;
    int m0 = blockIdx.y * 128, n0 = blockIdx.x * 64;
    int ar = tid >> 2, alq = tid & 3;

    ull accp[8][2];
#pragma unroll
    for (int i = 0; i < 8; i++) { accp[i][0] = 0ull; accp[i][1] = 0ull; }

    for (int k0 = 0; k0 < K; k0 += 16) {
        float4 a4a = *(const float4*)(A + (size_t)(m0 + ar) * lda + k0 + alq * 4);
        float4 a4b = *(const float4*)(A + (size_t)(m0 + ar + 64) * lda + k0 + alq * 4);
        float4 b4  = *(const float4*)(Bm + (size_t)(n0 + ar) * ldb + k0 + alq * 4);
        As[alq*4+0][ar] = a4a.x; As[alq*4+1][ar] = a4a.y;
        As[alq*4+2][ar] = a4a.z; As[alq*4+3][ar] = a4a.w;
        As[alq*4+0][ar+64] = a4b.x; As[alq*4+1][ar+64] = a4b.y;
        As[alq*4+2][ar+64] = a4b.z; As[alq*4+3][ar+64] = a4b.w;
        Bs[alq*4+0][ar] = b4.x; Bs[alq*4+1][ar] = b4.y;
        Bs[alq*4+2][ar] = b4.z; Bs[alq*4+3][ar] = b4.w;
        __syncthreads();
#pragma unroll
        for (int kk = 0; kk < 16; kk++) {
            float4 av0 = *(const float4*)&As[kk][ty * 8];
            float4 av1 = *(const float4*)&As[kk][ty * 8 + 4];
            float4 bv  = *(const float4*)&Bs[kk][tx * 4];
            ull b01, b23, s;
            PKU(b01, bv.x, bv.y); PKU(b23, bv.z, bv.w);
            PKU(s, av0.x, av0.x); ffma2(accp[0][0], s, b01); ffma2(accp[0][1], s, b23);
            PKU(s, av0.y, av0.y); ffma2(accp[1][0], s, b01); ffma2(accp[1][1], s, b23);
            PKU(s, av0.z, av0.z); ffma2(accp[2][0], s, b01); ffma2(accp[2][1], s, b23);
            PKU(s, av0.w, av0.w); ffma2(accp[3][0], s, b01); ffma2(accp[3][1], s, b23);
            PKU(s, av1.x, av1.x); ffma2(accp[4][0], s, b01); ffma2(accp[4][1], s, b23);
            PKU(s, av1.y, av1.y); ffma2(accp[5][0], s, b01); ffma2(accp[5][1], s, b23);
            PKU(s, av1.z, av1.z); ffma2(accp[6][0], s, b01); ffma2(accp[6][1], s, b23);
            PKU(s, av1.w, av1.w); ffma2(accp[7][0], s, b01); ffma2(accp[7][1], s, b23);
        }
        __syncthreads();
    }
    float bb[4];
#pragma unroll
    for (int j = 0; j < 4; j++) {
        int n = n0 + tx * 4 + j;
        bb[j] = (bias0 ? bias0[n] : 0.f) + (bias1 ? bias1[n] : 0.f);
    }
#pragma unroll
    for (int i = 0; i < 8; i++) {
        float2 lo = u2f(accp[i][0]), hi = u2f(accp[i][1]);
        float4 o4 = { lo.x + bb[0], lo.y + bb[1], hi.x + bb[2], hi.y + bb[3] };
        *(float4*)(C + (size_t)(m0 + ty * 8 + i) * ldc + n0 + tx * 4) = o4;
    }
}

// ---------------- fused keys+encdec GEMM: A = enc shared, N = 1024 ----------------
__global__ void __launch_bounds__(256) kt_gemm_enc(
    const float* __restrict__ A,
    const float* __restrict__ Watt, const float* __restrict__ Wdec,
    float* __restrict__ keys, float* __restrict__ encdec)
{
    __shared__ float As[16][132];
    __shared__ float Bs[16][68];
    int tid = threadIdx.x;
    int tx = tid & 15, ty = tid >> 4;
    int m0 = blockIdx.y * 128, n0 = blockIdx.x * 64;
    int ar = tid >> 2, alq = tid & 3;

    const float* Bm;
    float* C;
    int ldb, nbase;
    if (n0 < 512) { Bm = Watt; ldb = K2H; C = keys;   nbase = n0; }
    else          { Bm = Wdec; ldb = 1536; C = encdec; nbase = n0 - 512; }

    ull accp[8][2];
#pragma unroll
    for (int i = 0; i < 8; i++) { accp[i][0] = 0ull; accp[i][1] = 0ull; }

    for (int k0 = 0; k0 < K2H; k0 += 16) {
        float4 a4a = *(const float4*)(A + (size_t)(m0 + ar) * K2H + k0 + alq * 4);
        float4 a4b = *(const float4*)(A + (size_t)(m0 + ar + 64) * K2H + k0 + alq * 4);
        float4 b4  = *(const float4*)(Bm + (size_t)(nbase + ar) * ldb + k0 + alq * 4);
        As[alq*4+0][ar] = a4a.x; As[alq*4+1][ar] = a4a.y;
        As[alq*4+2][ar] = a4a.z; As[alq*4+3][ar] = a4a.w;
        As[alq*4+0][ar+64] = a4b.x; As[alq*4+1][ar+64] = a4b.y;
        As[alq*4+2][ar+64] = a4b.z; As[alq*4+3][ar+64] = a4b.w;
        Bs[alq*4+0][ar] = b4.x; Bs[alq*4+1][ar] = b4.y;
        Bs[alq*4+2][ar] = b4.z; Bs[alq*4+3][ar] = b4.w;
        __syncthreads();
#pragma unroll
        for (int kk = 0; kk < 16; kk++) {
            float4 av0 = *(const float4*)&As[kk][ty * 8];
            float4 av1 = *(const float4*)&As[kk][ty * 8 + 4];
            float4 bv  = *(const float4*)&Bs[kk][tx * 4];
            ull b01, b23, s;
            PKU(b01, bv.x, bv.y); PKU(b23, bv.z, bv.w);
            PKU(s, av0.x, av0.x); ffma2(accp[0][0], s, b01); ffma2(accp[0][1], s, b23);
            PKU(s, av0.y, av0.y); ffma2(accp[1][0], s, b01); ffma2(accp[1][1], s, b23);
            PKU(s, av0.z, av0.z); ffma2(accp[2][0], s, b01); ffma2(accp[2][1], s, b23);
            PKU(s, av0.w, av0.w); ffma2(accp[3][0], s, b01); ffma2(accp[3][1], s, b23);
            PKU(s, av1.x, av1.x); ffma2(accp[4][0], s, b01); ffma2(accp[4][1], s, b23);
            PKU(s, av1.y, av1.y); ffma2(accp[5][0], s, b01); ffma2(accp[5][1], s, b23);
            PKU(s, av1.z, av1.z); ffma2(accp[6][0], s, b01); ffma2(accp[6][1], s, b23);
            PKU(s, av1.w, av1.w); ffma2(accp[7][0], s, b01); ffma2(accp[7][1], s, b23);
        }
        __syncthreads();
    }
#pragma unroll
    for (int i = 0; i < 8; i++) {
        float2 lo = u2f(accp[i][0]), hi = u2f(accp[i][1]);
        float4 o4 = { lo.x, lo.y, hi.x, hi.y };
        *(float4*)(C + (size_t)(m0 + ty * 8 + i) * HH + nbase + tx * 4) = o4;
    }
}

// =================== persistent scan (512 threads, slim smem) ===================
// Grid = 148: CTAs [0,128) run the scan; CTAs [128,148) prepack W_vocab (overlap).
#define HSTR 514
#define CSTR 516
#define SM_WDH 65664
#define SM_ST  73984
#define SM_CS  142080
#define SM_MB  142592
#define SMEM_SCAN 142720

__global__ void __launch_bounds__(512) kt_scan(
    const int* __restrict__ mask,
    const float* __restrict__ Wih, const float* __restrict__ Whh,
    const float* __restrict__ Wdec, const float* __restrict__ bdec,
    const float* __restrict__ c0, const float* __restrict__ Wv)
{
    int c = blockIdx.x, tid = threadIdx.x;

    // ---- overlap CTAs: prepack W_vocab fragments while workers scan ----
    if (c >= NBLK) {
        int pc = c - NBLK;                       // 0..19
        const int TOTAL = 4000 * 32 * 32;
        int per = (TOTAL + 19) / 20;
        int lo = pc * per;
        int hi = min(lo + per, TOTAL);
        for (int i = lo + tid; i < hi; i += 512) {
            int lane = i & 31; int tile = i >> 5;
            int kt = tile & 31; int nrow = tile >> 5;
            int gid = lane >> 2, tg = lane & 3;
            const float* p = Wv + (size_t)(nrow * 8 + gid) * HH + kt * 16 + tg * 2;
            uint2 v; v.x = pk_bf2(p[0], p[1]); v.y = pk_bf2(p[8], p[9]);
            g_wswz[i] = v;
        }
        return;
    }

    extern __shared__ char smem[];
    float2* wg    = (float2*)smem;                 // [16][513]
    float*  wdh   = (float*)(smem + SM_WDH);       // [4][520]
    float*  stage = (float*)(smem + SM_ST);        // aliases
    float*  cs    = (float*)(smem + SM_CS);        // [128] cell state
    float*  mbias = (float*)(smem + SM_MB);        // [32]

    int bB = c & 31, qB = c >> 5;

    for (int idx = tid; idx < 16 * 512; idx += 512) {
        int r = idx >> 9, kp = idx & 511;
        int type = r >> 2, jj = r & 3;
        int g = type * 512 + c * 4 + jj;
        int k = kp * 2;
        float a, b2;
        if (k < 512) { a = Wih[g * 768 + 256 + k]; b2 = Wih[g * 768 + 257 + k]; }
        else         { a = Whh[g * 512 + k - 512]; b2 = Whh[g * 512 + k - 511]; }
        wg[r * 513 + kp] = make_float2(a, b2);
    }
    for (int idx = tid; idx < 4 * 512; idx += 512) {
        int jl = idx >> 9, k = idx & 511;
        wdh[jl * 520 + k] = Wdec[(size_t)(c * 4 + jl) * 1536 + 1024 + k];
    }
    if (tid < 32)
        mbias[tid] = (mask[bB * SSRC + qB * 32 + tid] > 0) ? 0.f : -1e9f;
    if (tid < 128)
        cs[tid] = c0[(tid >> 2) * HH + c * 4 + (tid & 3)];

    unsigned tgt = 0;
    __syncthreads();

    int ks = tid >> 5, gt = (tid >> 3) & 3, bt = tid & 7;

    for (int t = 0; t < TT; t++) {
        // ======== phase A ========
        {
            float gy0 = 0, gy1 = 0, gy2 = 0, gy3 = 0;
            if (tid < 128) {
                int b = tid >> 2, jj = tid & 3;
                const float* gy = g_gatesy + (size_t)(t * BB + b) * G4 + c * 4 + jj;
                gy0 = gy[0]; gy1 = gy[512]; gy2 = gy[1024]; gy3 = gy[1536];
            }
            ull a00=0,a01=0,a02=0,a03=0, a10=0,a11=0,a12=0,a13=0;
            ull a20=0,a21=0,a22=0,a23=0, a30=0,a31=0,a32=0,a33=0;
            const float2* gx2 = (const float2*)g_x;
#pragma unroll
            for (int half = 0; half < 2; half++) {
                for (int idx = tid; idx < 32 * 256; idx += 512) {
                    int b = idx >> 8, kp = idx & 255;
                    *(float2*)(stage + b * HSTR + kp * 2) = gx2[b * 512 + half * 256 + kp];
                }
                __syncthreads();
                const ull* w0 = (const ull*)(wg + (gt*4+0)*513) + half*256 + ks*16;
                const ull* w1 = (const ull*)(wg + (gt*4+1)*513) + half*256 + ks*16;
                const ull* w2 = (const ull*)(wg + (gt*4+2)*513) + half*256 + ks*16;
                const ull* w3 = (const ull*)(wg + (gt*4+3)*513) + half*256 + ks*16;
                const ull* x0 = (const ull*)(stage + (bt*4+0)*HSTR) + ks*16;
                const ull* x1 = (const ull*)(stage + (bt*4+1)*HSTR) + ks*16;
                const ull* x2 = (const ull*)(stage + (bt*4+2)*HSTR) + ks*16;
                const ull* x3 = (const ull*)(stage + (bt*4+3)*HSTR) + ks*16;
#pragma unroll
                for (int kp = 0; kp < 16; kp++) {
                    ull wa=w0[kp], wb=w1[kp], wc=w2[kp], wd=w3[kp];
                    ull xa=x0[kp], xb=x1[kp], xc=x2[kp], xd=x3[kp];
                    ffma2(a00,wa,xa); ffma2(a01,wa,xb); ffma2(a02,wa,xc); ffma2(a03,wa,xd);
                    ffma2(a10,wb,xa); ffma2(a11,wb,xb); ffma2(a12,wb,xc); ffma2(a13,wb,xd);
                    ffma2(a20,wc,xa); ffma2(a21,wc,xb); ffma2(a22,wc,xc); ffma2(a23,wc,xd);
                    ffma2(a30,wd,xa); ffma2(a31,wd,xb); ffma2(a32,wd,xc); ffma2(a33,wd,xd);
                }
                __syncthreads();
            }
            float* red16 = stage;
            float* gsum  = stage + 8320;
#define RSUM(v) ({ float2 f_ = u2f(v); f_.x + f_.y; })
            {
                float4 r0 = { RSUM(a00), RSUM(a01), RSUM(a02), RSUM(a03) };
                float4 r1 = { RSUM(a10), RSUM(a11), RSUM(a12), RSUM(a13) };
                float4 r2 = { RSUM(a20), RSUM(a21), RSUM(a22), RSUM(a23) };
                float4 r3 = { RSUM(a30), RSUM(a31), RSUM(a32), RSUM(a33) };
                *(float4*)(red16 + ks*520 + (gt*4+0)*32 + bt*4) = r0;
                *(float4*)(red16 + ks*520 + (gt*4+1)*32 + bt*4) = r1;
                *(float4*)(red16 + ks*520 + (gt*4+2)*32 + bt*4) = r2;
                *(float4*)(red16 + ks*520 + (gt*4+3)*32 + bt*4) = r3;
            }
#undef RSUM
            __syncthreads();
            {
                int r = tid >> 5, b = tid & 31;
                float s = 0.f;
#pragma unroll
                for (int q = 0; q < 16; q++) s += red16[q*520 + r*32 + b];
                gsum[r * 33 + b] = s;
            }
            __syncthreads();
            if (tid < 128) {
                int b = tid >> 2, jj = tid & 3;
                float vi = gsum[jj * 33 + b]        + gy0;
                float vf = gsum[(4 + jj) * 33 + b]  + gy1;
                float vg = gsum[(8 + jj) * 33 + b]  + gy2;
                float vo = gsum[(12 + jj) * 33 + b] + gy3;
                float cc = cs[tid];
                float ig = 1.f / (1.f + __expf(-vi));
                float fg = 1.f / (1.f + __expf(-vf));
                float gg = tanhf(vg);
                float og = 1.f / (1.f + __expf(-vo));
                float cn = fg * cc + ig * gg;
                float hn = og * tanhf(cn);
                cs[tid] = cn;
                g_x[b * K2H + HH + c * 4 + jj] = hn;
            }
        }
        gbar(++tgt);

        // ======== phase B ========
        {
            float* hs = stage;
            float* sc = stage + 512;
            float* es = stage + 576;
            hs[tid] = g_x[bB * K2H + HH + tid];
            __syncthreads();

            int w = tid >> 5, lane = tid & 31;
            float4 hreg[4];
#pragma unroll
            for (int p = 0; p < 4; p++)
                hreg[p] = *(const float4*)(hs + (lane + p * 32) * 4);
#pragma unroll
            for (int si = 0; si < 2; si++) {
                int sl = w * 2 + si;
                const float4* kp = (const float4*)(g_keys +
                    ((size_t)bB * SSRC + qB * 32 + sl) * HH);
                float acc = 0.f;
#pragma unroll
                for (int p = 0; p < 4; p++) {
                    float4 kv = kp[lane + p * 32];
                    acc += hreg[p].x*kv.x + hreg[p].y*kv.y + hreg[p].z*kv.z + hreg[p].w*kv.w;
                }
#pragma unroll
                for (int off = 16; off; off >>= 1)
                    acc += __shfl_down_sync(0xffffffffu, acc, off);
                if (lane == 0) sc[sl] = acc + mbias[sl];
            }
            __syncthreads();

            if (tid < 32) {
                float v = sc[tid];
                float m = v;
#pragma unroll
                for (int off = 16; off; off >>= 1)
                    m = fmaxf(m, __shfl_xor_sync(0xffffffffu, m, off));
                float e = __expf(v - m);
                es[tid] = e;
                float Z = e;
#pragma unroll
                for (int off = 16; off; off >>= 1)
                    Z += __shfl_xor_sync(0xffffffffu, Z, off);
                if (tid == 0) g_bstats[qB * 32 + bB] = make_float2(m, Z);
            }
            __syncthreads();

            {
                int j = tid;
                const float* ed = g_encdec + ((size_t)bB * SSRC + qB * 32) * HH;
                float p = 0.f;
#pragma unroll 8
                for (int s = 0; s < 32; s++) p += es[s] * ed[(size_t)s * HH + j];
                g_pctx[(qB * 32 + bB) * HH + j] = p;
            }
        }
        gbar(++tgt);

        // ======== phase C ========
        {
            for (int idx = tid; idx < 32 * 128; idx += 512) {
                int b = idx >> 7, k4 = idx & 127;
                *(float4*)(stage + b * CSTR + k4 * 4) =
                    *(const float4*)(g_x + b * K2H + HH + k4 * 4);
            }
            __syncthreads();
            float* red2 = stage + 16512;
            {
                int kk = tid >> 7, cell = tid & 127, bC = cell >> 2, jl = cell & 3;
                const float4* wp = (const float4*)(wdh + jl * 520 + kk * 128);
                const float4* hp = (const float4*)(stage + bC * CSTR + kk * 128);
                float acc = 0.f;
#pragma unroll 8
                for (int k4 = 0; k4 < 32; k4++) {
                    float4 wv = wp[k4], hv = hp[k4];
                    acc += wv.x*hv.x + wv.y*hv.y + wv.z*hv.z + wv.w*hv.w;
                }
                red2[kk * 128 + cell] = acc;
            }
            __syncthreads();
            if (tid < 128) {
                float wsum = red2[tid] + red2[128 + tid] + red2[256 + tid] + red2[384 + tid];
                int b = tid >> 2, jl = tid & 3, j = c * 4 + jl;
                float2 st0 = g_bstats[b], st1 = g_bstats[32 + b];
                float2 st2 = g_bstats[64 + b], st3 = g_bstats[96 + b];
                float M = fmaxf(fmaxf(st0.x, st1.x), fmaxf(st2.x, st3.x));
                float w0 = __expf(st0.x - M), w1 = __expf(st1.x - M);
                float w2 = __expf(st2.x - M), w3 = __expf(st3.x - M);
                float den = st0.y*w0 + st1.y*w1 + st2.y*w2 + st3.y*w3;
                float num = w0 * g_pctx[(0*32+b)*HH + j] + w1 * g_pctx[(1*32+b)*HH + j]
                          + w2 * g_pctx[(2*32+b)*HH + j] + w3 * g_pctx[(3*32+b)*HH + j];
                float o = tanhf(num / den + wsum + bdec[j]);
                g_x[b * K2H + j] = o;
                g_oseq[((size_t)b * TT + t) * HH + j] = o;
            }
        }
        gbar(++tgt);
    }
}

// ---------------- vocab GEMM: smem-staged fragments + fused sum-exp partials ----------------
#define MMA16816(d0,d1,d2,d3,A0,A1,A2,A3,B0,B1) \
    asm volatile("mma.sync.aligned.m16n8k16.row.col.f32.bf16.bf16.f32 " \
        "{%0,%1,%2,%3}, {%4,%5,%6,%7}, {%8,%9}, {%0,%1,%2,%3};" \
        : "+f"(d0), "+f"(d1), "+f"(d2), "+f"(d3) \
        : "r"(A0), "r"(A1), "r"(A2), "r"(A3), "r"(B0), "r"(B1))

__global__ void __launch_bounds__(256) kt_vocab_gemm(
    float* __restrict__ out, const float* __restrict__ bvocab)
{
    __shared__ uint4 Asm[2][256];    // [buf][mrow(8)*32 + lane]
    __shared__ uint2 Bsm[2][512];    // [buf][nrow(16)*32 + lane]
    __shared__ float rowsum[128][4];

    int nb = blockIdx.x, mb = blockIdx.y;
    int tid = threadIdx.x;
    int wid = tid >> 5, lane = tid & 31;
    int wm = wid >> 2, wn = wid & 3;
    int gid = lane >> 2, tg = lane & 3;

    if (tid < 128) {
#pragma unroll
        for (int w = 0; w < 4; w++) rowsum[tid][w] = 0.f;
    }

    int mrow0 = mb * 8;      // block A-fragment rows
    int nrow0 = nb * 16;     // block B-fragment rows
    int lrow = tid >> 5;     // loader row 0..7
    int llane = tid & 31;

    float acc[4][4][4];
#pragma unroll
    for (int i = 0; i < 4; i++)
#pragma unroll
        for (int j = 0; j < 4; j++)
#pragma unroll
            for (int r = 0; r < 4; r++) acc[i][j][r] = 0.f;

    // preload kt=0
    uint4 aReg = g_oswz[(((mrow0 + lrow) * 32 + 0) << 5) + llane];
    uint2 b0Reg = g_wswz[(((size_t)(nrow0 + lrow) * 32 + 0) << 5) + llane];
    uint2 b1Reg = g_wswz[(((size_t)(nrow0 + 8 + lrow) * 32 + 0) << 5) + llane];
    Asm[0][tid] = aReg;
    Bsm[0][lrow * 32 + llane] = b0Reg;
    Bsm[0][(8 + lrow) * 32 + llane] = b1Reg;
    __syncthreads();

    for (int kt = 0; kt < 32; kt++) {
        int cur = kt & 1, nxt = cur ^ 1;
        if (kt < 31) {
            aReg  = g_oswz[(((mrow0 + lrow) * 32 + kt + 1) << 5) + llane];
            b0Reg = g_wswz[(((size_t)(nrow0 + lrow) * 32 + kt + 1) << 5) + llane];
            b1Reg = g_wswz[(((size_t)(nrow0 + 8 + lrow) * 32 + kt + 1) << 5) + llane];
        }
        uint4 af[4];
        uint2 bf[4];
#pragma unroll
        for (int mt = 0; mt < 4; mt++)
            af[mt] = Asm[cur][(wm * 4 + mt) * 32 + lane];
#pragma unroll
        for (int nt = 0; nt < 4; nt++)
            bf[nt] = Bsm[cur][(wn * 4 + nt) * 32 + lane];
#pragma unroll
        for (int mt = 0; mt < 4; mt++)
#pragma unroll
            for (int nt = 0; nt < 4; nt++)
                MMA16816(acc[mt][nt][0], acc[mt][nt][1], acc[mt][nt][2], acc[mt][nt][3],
                         af[mt].x, af[mt].y, af[mt].z, af[mt].w, bf[nt].x, bf[nt].y);
        if (kt < 31) {
            __syncthreads();
            Asm[nxt][tid] = aReg;
            Bsm[nxt][lrow * 32 + llane] = b0Reg;
            Bsm[nxt][(8 + lrow) * 32 + llane] = b1Reg;
            __syncthreads();
        }
    }

    int m_warp = mb * 128 + wm * 64;
    int n_warp = nb * 128 + wn * 32;
#pragma unroll
    for (int mt = 0; mt < 4; mt++) {
        float s0 = 0.f, s1 = 0.f;
#pragma unroll
        for (int nt = 0; nt < 4; nt++) {
            int r = m_warp + mt * 16 + gid;
            int ci = n_warp + nt * 8 + tg * 2;
            float bv0 = bvocab[ci], bv1 = bvocab[ci + 1];
            float v00 = acc[mt][nt][0] + bv0, v01 = acc[mt][nt][1] + bv1;
            float v10 = acc[mt][nt][2] + bv0, v11 = acc[mt][nt][3] + bv1;
            float2 w0 = { v00, v01 }, w1 = { v10, v11 };
            *reinterpret_cast<float2*>(out + (size_t)r * VV + ci) = w0;
            *reinterpret_cast<float2*>(out + (size_t)(r + 8) * VV + ci) = w1;
            s0 += __expf(v00) + __expf(v01);
            s1 += __expf(v10) + __expf(v11);
        }
        s0 += __shfl_xor_sync(0xffffffffu, s0, 1);
        s0 += __shfl_xor_sync(0xffffffffu, s0, 2);
        s1 += __shfl_xor_sync(0xffffffffu, s1, 1);
        s1 += __shfl_xor_sync(0xffffffffu, s1, 2);
        if (tg == 0) {
            rowsum[wm * 64 + mt * 16 + gid][wn] = s0;
            rowsum[wm * 64 + mt * 16 + gid + 8][wn] = s1;
        }
    }
    __syncthreads();
    if (tid < 128) {
        float p = rowsum[tid][0] + rowsum[tid][1] + rowsum[tid][2] + rowsum[tid][3];
        g_partial[(size_t)(mb * 128 + tid) * NTILE + nb] = p;
    }
}

__global__ void __launch_bounds__(256) kt_lsfinal(float* __restrict__ out) {
    int row = blockIdx.x, tid = threadIdx.x;
    __shared__ float red[256];
    __shared__ float lse_s;
    float s = 0.f;
    for (int i = tid; i < NTILE; i += 256) s += g_partial[(size_t)row * NTILE + i];
    red[tid] = s;
    __syncthreads();
#pragma unroll
    for (int off = 128; off; off >>= 1) {
        if (tid < off) red[tid] += red[tid + off];
        __syncthreads();
    }
    if (tid == 0) lse_s = logf(red[0]);
    __syncthreads();
    float lse = lse_s;
    float* p = out + (size_t)row * VV;
    for (int i = tid * 4; i < VV; i += 256 * 4) {
        float4 v = *reinterpret_cast<float4*>(p + i);
        v.x -= lse; v.y -= lse; v.z -= lse; v.w -= lse;
        *reinterpret_cast<float4*>(p + i) = v;
    }
}

// ---------------- launch ----------------
extern "C" void kernel_launch(void* const* d_in, const int* in_sizes, int n_in,
                              void* d_out, int out_size)
{
    const float* enc     = (const float*)d_in[0];
    const int*   mask    = (const int*)  d_in[1];
    const int*   ids     = (const int*)  d_in[2];
    const float* h0      = (const float*)d_in[3];
    const float* c0      = (const float*)d_in[4];
    const float* emb     = (const float*)d_in[5];
    const float* W_ih    = (const float*)d_in[6];
    const float* b_ih    = (const float*)d_in[7];
    const float* W_hh    = (const float*)d_in[8];
    const float* b_hh    = (const float*)d_in[9];
    const float* W_att   = (const float*)d_in[10];
    const float* W_dec   = (const float*)d_in[11];
    const float* b_dec   = (const float*)d_in[12];
    const float* W_vocab = (const float*)d_in[13];
    const float* b_vocab = (const float*)d_in[14];
    float* out = (float*)d_out;

    cudaFuncSetAttribute(kt_scan, cudaFuncAttributeMaxDynamicSharedMemorySize, SMEM_SCAN);

    kt_init<<<(BB*HH + 255)/256, 256>>>(h0);
    kt_gather<<<(TT*BB*EE + 255)/256, 256>>>(emb, ids);

    {
        float* keysp; cudaGetSymbolAddress((void**)&keysp, g_keys);
        float* edp;   cudaGetSymbolAddress((void**)&edp, g_encdec);
        float* embp;  cudaGetSymbolAddress((void**)&embp, g_embseq);
        float* gyp;   cudaGetSymbolAddress((void**)&gyp, g_gatesy);
        kt_gemm_enc<<<dim3(16, 32), 256>>>(enc, W_att, W_dec, keysp, edp);
        kt_gemm_nt<<<dim3(32, 32), 256>>>(embp, EE, W_ih, 768, gyp, G4, EE, b_ih, b_hh);
    }

    kt_scan<<<NSCAN, 512, SMEM_SCAN>>>(mask, W_ih, W_hh, W_dec, b_dec, c0, W_vocab);

    kt_prepack_o<<<(256*32*32 + 255)/256, 256>>>();
    kt_vocab_gemm<<<dim3(NTILE, (BB*TT)/128), 256>>>(out, b_vocab);
    kt_lsfinal<<<BB*TT, 256>>>(out);
}